// round 11
// baseline (speedup 1.0000x reference)
#include <cuda_runtime.h>
#include <cuda_bf16.h>
#include <math.h>

// Problem constants (fixed by the dataset)
#define NSEQ 4096
#define DIM  768
#define NH   8
#define HD   96
#define TD   2304
#define MAXB 2
#define SCALE 0.036084391824351615f   // 768^-0.5

// Scratch: [3][B*NH][NSEQ][HD]
__device__ float g_qkv[3ull * MAXB * NH * NSEQ * HD];

// ---------------- helpers ----------------
__device__ __forceinline__ unsigned tf32u(float x) {
    unsigned y; asm("cvt.rna.tf32.f32 %0, %1;" : "=r"(y) : "f"(x)); return y;
}
// D += A(16x8,row,tf32) * B(8x8,col,tf32), fp32 accum
__device__ __forceinline__ void mma8(float* c, const unsigned* a, unsigned b0, unsigned b1) {
    asm volatile(
        "mma.sync.aligned.m16n8k8.row.col.f32.tf32.tf32.f32 "
        "{%0,%1,%2,%3}, {%4,%5,%6,%7}, {%8,%9}, {%0,%1,%2,%3};"
        : "+f"(c[0]), "+f"(c[1]), "+f"(c[2]), "+f"(c[3])
        : "r"(a[0]), "r"(a[1]), "r"(a[2]), "r"(a[3]), "r"(b0), "r"(b1));
}
__device__ __forceinline__ void cp16(unsigned dst, const void* src) {
    asm volatile("cp.async.cg.shared.global [%0], [%1], 16;" :: "r"(dst), "l"(src));
}
__device__ __forceinline__ void cp_commit() {
    asm volatile("cp.async.commit_group;" ::: "memory");
}
__device__ __forceinline__ void cp_wait0() {
    asm volatile("cp.async.wait_group 0;" ::: "memory");
}

// ---------------------------------------------------------------------------
// Kernel 1: QKV GEMM (TF32 mma).  C[8192,2304] = X @ W + bias -> scatter.
// CTA 256 thr (8 warps), tile 128x128, k-step 32, register double buffering.
// ---------------------------------------------------------------------------
#define XS_STR 36     // == 4 (mod 32): conflict-free A-frag loads
#define WS_STR 136    // == 8 (mod 32): conflict-free B-frag loads

__global__ __launch_bounds__(256, 2) void qkv_gemm_kernel(
    const float* __restrict__ X, const float* __restrict__ W,
    const float* __restrict__ bias, int B)
{
    __shared__ unsigned Xs[128 * XS_STR];
    __shared__ unsigned Ws[32 * WS_STR];

    const int tid  = threadIdx.x;
    const int lane = tid & 31;
    const int gid  = lane >> 2;
    const int tig  = lane & 3;
    const int w    = tid >> 5;
    const int wm   = w >> 1;               // 0..3
    const int wn   = w & 1;                // 0..1
    const int row0 = blockIdx.y * 128;
    const int col0 = blockIdx.x * 128;

    float c[2][8][4];
#pragma unroll
    for (int mt = 0; mt < 2; mt++)
#pragma unroll
        for (int nt = 0; nt < 8; nt++)
#pragma unroll
            for (int j = 0; j < 4; j++) c[mt][nt][j] = 0.f;

    const int xr = tid >> 1, xk = (tid & 1) * 16;   // X fill: row, k-slice
    const int wr = tid >> 3, wc = (tid & 7) * 16;   // W fill: k-row, col-slice

    float4 xs4[4], ws4[4];
    // prologue load of k-tile 0
    {
        const float* xsrc = X + (size_t)(row0 + xr) * DIM + xk;
        const float* wsrc = W + (size_t)wr * TD + col0 + wc;
#pragma unroll
        for (int i = 0; i < 4; i++) { xs4[i] = *(const float4*)(xsrc + 4 * i);
                                      ws4[i] = *(const float4*)(wsrc + 4 * i); }
    }

    for (int k0 = 0; k0 < DIM; k0 += 32) {
        // store staged tile (tf32-rounded)
#pragma unroll
        for (int i = 0; i < 4; i++) {
            *(uint4*)&Xs[xr * XS_STR + xk + 4 * i] =
                make_uint4(tf32u(xs4[i].x), tf32u(xs4[i].y), tf32u(xs4[i].z), tf32u(xs4[i].w));
            *(uint4*)&Ws[wr * WS_STR + wc + 4 * i] =
                make_uint4(tf32u(ws4[i].x), tf32u(ws4[i].y), tf32u(ws4[i].z), tf32u(ws4[i].w));
        }
        __syncthreads();

        // prefetch next k-tile into registers (overlaps compute)
        if (k0 + 32 < DIM) {
            const float* xsrc = X + (size_t)(row0 + xr) * DIM + k0 + 32 + xk;
            const float* wsrc = W + (size_t)(k0 + 32 + wr) * TD + col0 + wc;
#pragma unroll
            for (int i = 0; i < 4; i++) { xs4[i] = *(const float4*)(xsrc + 4 * i);
                                          ws4[i] = *(const float4*)(wsrc + 4 * i); }
        }

#pragma unroll
        for (int kc = 0; kc < 4; kc++) {
            unsigned a[2][4];
#pragma unroll
            for (int mt = 0; mt < 2; mt++) {
                const unsigned* qp = &Xs[(wm * 32 + mt * 16 + gid) * XS_STR + kc * 8 + tig];
                a[mt][0] = qp[0];
                a[mt][2] = qp[4];
                a[mt][1] = qp[8 * XS_STR];
                a[mt][3] = qp[8 * XS_STR + 4];
            }
#pragma unroll
            for (int nt = 0; nt < 8; nt++) {
                unsigned b0 = Ws[(kc * 8 + tig)     * WS_STR + wn * 64 + nt * 8 + gid];
                unsigned b1 = Ws[(kc * 8 + tig + 4) * WS_STR + wn * 64 + nt * 8 + gid];
                mma8(c[0][nt], a[0], b0, b1);
                mma8(c[1][nt], a[1], b0, b1);
            }
        }
        __syncthreads();
    }

    // epilogue: bias + scatter into g_qkv[s][b*NH+h][n][d]
    const size_t per_s = (size_t)B * NH * NSEQ * HD;
#pragma unroll
    for (int mt = 0; mt < 2; mt++) {
        const int r_lo = row0 + wm * 32 + mt * 16 + gid;
        const int r_hi = r_lo + 8;
#pragma unroll
        for (int nt = 0; nt < 8; nt++) {
            const int cA = col0 + wn * 64 + nt * 8 + 2 * tig;
#pragma unroll
            for (int e = 0; e < 2; e++) {
                const int cc = cA + e;
                const float bb = __ldg(&bias[cc]);
                const int s  = cc / DIM;
                const int rem = cc - s * DIM;
                const int h  = rem / HD;
                const int d  = rem - h * HD;
#pragma unroll
                for (int half = 0; half < 2; half++) {
                    const int r = half ? r_hi : r_lo;
                    const int b = r >> 12;
                    const int n = r & 4095;
                    const float v = c[mt][nt][half * 2 + e] + bb;
                    g_qkv[(size_t)s * per_s +
                          (((size_t)(b * NH + h)) * NSEQ + n) * HD + d] = v;
                }
            }
        }
    }
}

// ---------------------------------------------------------------------------
// Kernel 2: flash attention, TF32 mma + cp.async double-buffered K/V.
// grid = (NSEQ/128, B*NH), CTA 256 thr (8 warps), q-tile 128 (16 rows/warp),
// kv-tile 32.  smem 103.4 KB -> 2 CTAs/SM (16 warps/SM, cross-CTA overlap).
// K/V stored RAW f32 (mma reads tf32 bits; RZ truncation).
// smem words: Qs 128*100 | K0 32*100 | K1 32*100 | V0 32*104 | V1 32*104
// ---------------------------------------------------------------------------
#define QT 128
#define KVT 32
#define QS_STR 100
#define KS_STR 100
#define VS_STR 104
#define KWORDS (KVT * KS_STR)         // 3200
#define VWORDS (KVT * VS_STR)         // 3328
#define OFF_K  (QT * QS_STR)          // 12800
#define OFF_V  (OFF_K + 2 * KWORDS)   // 19200
#define ATTN_SMEM_WORDS (OFF_V + 2 * VWORDS)
#define ATTN_SMEM_BYTES (ATTN_SMEM_WORDS * 4)   // 103424

__global__ __launch_bounds__(256, 2) void attn_kernel(
    float* __restrict__ out, int B)
{
    extern __shared__ unsigned asmem[];
    unsigned* Qs = asmem;
    const unsigned smemA = (unsigned)__cvta_generic_to_shared(asmem);

    const int tid  = threadIdx.x;
    const int lane = tid & 31;
    const int gid  = lane >> 2;
    const int tig  = lane & 3;
    const int w    = tid >> 5;                  // 0..7: rows [16w, 16w+16)
    const int bh   = blockIdx.y;
    const int q0   = blockIdx.x * QT;

    const size_t per_s = (size_t)B * NH * NSEQ * HD;
    const float* Qg = g_qkv + (size_t)bh * NSEQ * HD;
    const float* Kg = Qg + per_s;
    const float* Vg = Kg + per_s;

    // ---- precompute cp.async fill mapping (constant across tiles) ----
    // 1536 16B-chunks per kv-tile: [0,768) -> K rows, [768,1536) -> V rows
    int      fArr[6];
    unsigned fSoff[6];     // word offset inside the K or V buffer
    unsigned fGoff[6];     // float offset inside the 32x96 global tile
#pragma unroll
    for (int i = 0; i < 6; i++) {
        int c   = tid + i * 256;
        int arr = (c >= 768);
        int rem = c - (arr ? 768 : 0);
        int r   = rem / 24;
        int ch  = rem - r * 24;
        fArr[i]  = arr;
        fSoff[i] = arr ? (unsigned)(r * VS_STR + ch * 4) : (unsigned)(r * KS_STR + ch * 4);
        fGoff[i] = (unsigned)(r * HD + ch * 4);
    }

    // ---- issue fills for tile 0 (buf 0) ----
    {
        const unsigned kB = smemA + OFF_K * 4;
        const unsigned vB = smemA + OFF_V * 4;
#pragma unroll
        for (int i = 0; i < 6; i++) {
            const float* src = (fArr[i] ? Vg : Kg) + fGoff[i];
            cp16((fArr[i] ? vB : kB) + fSoff[i] * 4, src);
        }
        cp_commit();
    }

    // ---- load Q tile (tf32-rounded, RNA) ----
    {
        const int row = tid >> 1, dp = (tid & 1) * 48;
        const float* src = Qg + (size_t)(q0 + row) * HD + dp;
#pragma unroll
        for (int i = 0; i < 12; i++) {
            float4 v = *(const float4*)(src + 4 * i);
            *(uint4*)&Qs[row * QS_STR + dp + 4 * i] =
                make_uint4(tf32u(v.x), tf32u(v.y), tf32u(v.z), tf32u(v.w));
        }
    }

    // softmax state + O accumulators
    float m_lo = -INFINITY, m_hi = -INFINITY, l_lo = 0.f, l_hi = 0.f;
    float o[12][4];
#pragma unroll
    for (int nt = 0; nt < 12; nt++)
#pragma unroll
        for (int j = 0; j < 4; j++) o[nt][j] = 0.f;

    // shuffle source lanes for C->A fragment conversion
    const int srcA = (lane & 28) | (tig >> 1);
    const int srcB = srcA + 2;
    const bool oddl = lane & 1;

    const unsigned* qbase = &Qs[(w * 16 + gid) * QS_STR + tig];

    for (int t = 0; t < NSEQ / KVT; ++t) {
        const int buf = t & 1;
        cp_wait0();
        __syncthreads();              // tile t resident; prev bufs free

        // issue fills for tile t+1 into the other buffers (overlaps compute)
        if (t + 1 < NSEQ / KVT) {
            const int nbuf = buf ^ 1;
            const size_t gbase = (size_t)(t + 1) * KVT * HD;
            const unsigned kB = smemA + (OFF_K + nbuf * KWORDS) * 4;
            const unsigned vB = smemA + (OFF_V + nbuf * VWORDS) * 4;
#pragma unroll
            for (int i = 0; i < 6; i++) {
                const float* src = (fArr[i] ? Vg : Kg) + gbase + fGoff[i];
                cp16((fArr[i] ? vB : kB) + fSoff[i] * 4, src);
            }
            cp_commit();
        }

        const unsigned* Kc = asmem + OFF_K + buf * KWORDS;
        const unsigned* Vc = asmem + OFF_V + buf * VWORDS;

        // ---- S = Q K^T : 12 k-chunks x 4 n-tiles ----
        float s[4][4];
#pragma unroll
        for (int nt = 0; nt < 4; nt++)
#pragma unroll
            for (int j = 0; j < 4; j++) s[nt][j] = 0.f;

#pragma unroll
        for (int kc = 0; kc < 12; kc++) {
            unsigned a[4];
            a[0] = qbase[kc * 8];
            a[2] = qbase[kc * 8 + 4];
            a[1] = qbase[8 * QS_STR + kc * 8];
            a[3] = qbase[8 * QS_STR + kc * 8 + 4];
#pragma unroll
            for (int nt = 0; nt < 4; nt++) {
                const unsigned* kp = &Kc[(nt * 8 + gid) * KS_STR + kc * 8 + tig];
                mma8(s[nt], a, kp[0], kp[4]);
            }
        }

        // ---- online softmax ----
        float rmax_lo = fmaxf(fmaxf(s[0][0], s[0][1]), fmaxf(s[1][0], s[1][1]));
        float rmax_hi = fmaxf(fmaxf(s[0][2], s[0][3]), fmaxf(s[1][2], s[1][3]));
        rmax_lo = fmaxf(rmax_lo, fmaxf(fmaxf(s[2][0], s[2][1]), fmaxf(s[3][0], s[3][1])));
        rmax_hi = fmaxf(rmax_hi, fmaxf(fmaxf(s[2][2], s[2][3]), fmaxf(s[3][2], s[3][3])));
        rmax_lo = fmaxf(rmax_lo, __shfl_xor_sync(0xffffffffu, rmax_lo, 1));
        rmax_lo = fmaxf(rmax_lo, __shfl_xor_sync(0xffffffffu, rmax_lo, 2));
        rmax_hi = fmaxf(rmax_hi, __shfl_xor_sync(0xffffffffu, rmax_hi, 1));
        rmax_hi = fmaxf(rmax_hi, __shfl_xor_sync(0xffffffffu, rmax_hi, 2));

        const float mn_lo = fmaxf(m_lo, rmax_lo * SCALE);
        const float mn_hi = fmaxf(m_hi, rmax_hi * SCALE);
        const float corr_lo = __expf(m_lo - mn_lo);
        const float corr_hi = __expf(m_hi - mn_hi);
        m_lo = mn_lo; m_hi = mn_hi;

        float sum_lo = 0.f, sum_hi = 0.f;
#pragma unroll
        for (int nt = 0; nt < 4; nt++) {
            float e0 = __expf(fmaf(s[nt][0], SCALE, -mn_lo));
            float e1 = __expf(fmaf(s[nt][1], SCALE, -mn_lo));
            float e2 = __expf(fmaf(s[nt][2], SCALE, -mn_hi));
            float e3 = __expf(fmaf(s[nt][3], SCALE, -mn_hi));
            sum_lo += e0 + e1;
            sum_hi += e2 + e3;
            s[nt][0] = __uint_as_float(tf32u(e0));
            s[nt][1] = __uint_as_float(tf32u(e1));
            s[nt][2] = __uint_as_float(tf32u(e2));
            s[nt][3] = __uint_as_float(tf32u(e3));
        }
        sum_lo += __shfl_xor_sync(0xffffffffu, sum_lo, 1);
        sum_lo += __shfl_xor_sync(0xffffffffu, sum_lo, 2);
        sum_hi += __shfl_xor_sync(0xffffffffu, sum_hi, 1);
        sum_hi += __shfl_xor_sync(0xffffffffu, sum_hi, 2);
        l_lo = l_lo * corr_lo + sum_lo;
        l_hi = l_hi * corr_hi + sum_hi;

#pragma unroll
        for (int nt = 0; nt < 12; nt++) {
            o[nt][0] *= corr_lo; o[nt][1] *= corr_lo;
            o[nt][2] *= corr_hi; o[nt][3] *= corr_hi;
        }

        // ---- O += P @ V : 4 k-chunks x 12 d-tiles ----
#pragma unroll
        for (int kc = 0; kc < 4; kc++) {
            float p0 = s[kc][0], p1 = s[kc][1], p2 = s[kc][2], p3 = s[kc][3];
            float t0 = __shfl_sync(0xffffffffu, p0, srcA);
            float t1 = __shfl_sync(0xffffffffu, p1, srcA);
            float t2 = __shfl_sync(0xffffffffu, p2, srcA);
            float t3 = __shfl_sync(0xffffffffu, p3, srcA);
            float u0 = __shfl_sync(0xffffffffu, p0, srcB);
            float u1 = __shfl_sync(0xffffffffu, p1, srcB);
            float u2 = __shfl_sync(0xffffffffu, p2, srcB);
            float u3 = __shfl_sync(0xffffffffu, p3, srcB);
            unsigned a[4];
            a[0] = __float_as_uint(oddl ? t1 : t0);
            a[1] = __float_as_uint(oddl ? t3 : t2);
            a[2] = __float_as_uint(oddl ? u1 : u0);
            a[3] = __float_as_uint(oddl ? u3 : u2);
#pragma unroll
            for (int nt = 0; nt < 12; nt++) {
                const unsigned* vp = &Vc[(kc * 8 + tig) * VS_STR + nt * 8 + gid];
                mma8(o[nt], a, vp[0], vp[4 * VS_STR]);
            }
        }
    }

    // ---- epilogue ----
    const int b = bh >> 3;
    const int h = bh & 7;
    const int r_lo = q0 + w * 16 + gid;
    const int r_hi = r_lo + 8;
    const float inv_lo = 1.f / l_lo;
    const float inv_hi = 1.f / l_hi;
    float* out_lo = out + ((size_t)b * NSEQ + r_lo) * DIM + h * HD;
    float* out_hi = out + ((size_t)b * NSEQ + r_hi) * DIM + h * HD;
#pragma unroll
    for (int nt = 0; nt < 12; nt++) {
        const int d = nt * 8 + 2 * tig;
        *(float2*)&out_lo[d] = make_float2(o[nt][0] * inv_lo, o[nt][1] * inv_lo);
        *(float2*)&out_hi[d] = make_float2(o[nt][2] * inv_hi, o[nt][3] * inv_hi);
    }
}

// ---------------------------------------------------------------------------
extern "C" void kernel_launch(void* const* d_in, const int* in_sizes, int n_in,
                              void* d_out, int out_size)
{
    const float* x    = (const float*)d_in[0];   // (B, N, 768)
    const float* Wqkv = (const float*)d_in[1];   // (768, 2304)
    const float* bqkv = (const float*)d_in[2];   // (2304,)
    float* out = (float*)d_out;

    const int B = in_sizes[0] / (NSEQ * DIM);

    // QKV projection + scatter
    {
        dim3 grid(TD / 128, (B * NSEQ) / 128);
        qkv_gemm_kernel<<<grid, 256>>>(x, Wqkv, bqkv, B);
    }

    // flash attention
    {
        cudaFuncSetAttribute(attn_kernel,
                             cudaFuncAttributeMaxDynamicSharedMemorySize,
                             ATTN_SMEM_BYTES);
        dim3 grid(NSEQ / QT, B * NH);
        attn_kernel<<<grid, 256, ATTN_SMEM_BYTES>>>(out, B);
    }
}

// round 13
// speedup vs baseline: 1.1814x; 1.1814x over previous
#include <cuda_runtime.h>
#include <cuda_bf16.h>
#include <math.h>

// Problem constants (fixed by the dataset)
#define NSEQ 4096
#define DIM  768
#define NH   8
#define HD   96
#define TD   2304
#define MAXB 2
#define SCALE 0.036084391824351615f   // 768^-0.5

// Scratch: [3][B*NH][NSEQ][HD]  (holds tf32-prerounded bits)
__device__ float g_qkv[3ull * MAXB * NH * NSEQ * HD];

// ---------------- helpers ----------------
__device__ __forceinline__ unsigned tf32u(float x) {
    unsigned y; asm("cvt.rna.tf32.f32 %0, %1;" : "=r"(y) : "f"(x)); return y;
}
// D += A(16x8,row,tf32) * B(8x8,col,tf32), fp32 accum
__device__ __forceinline__ void mma8(float* c, const unsigned* a, unsigned b0, unsigned b1) {
    asm volatile(
        "mma.sync.aligned.m16n8k8.row.col.f32.tf32.tf32.f32 "
        "{%0,%1,%2,%3}, {%4,%5,%6,%7}, {%8,%9}, {%0,%1,%2,%3};"
        : "+f"(c[0]), "+f"(c[1]), "+f"(c[2]), "+f"(c[3])
        : "r"(a[0]), "r"(a[1]), "r"(a[2]), "r"(a[3]), "r"(b0), "r"(b1));
}
__device__ __forceinline__ void cp16(unsigned dst, const void* src) {
    asm volatile("cp.async.cg.shared.global [%0], [%1], 16;" :: "r"(dst), "l"(src));
}
__device__ __forceinline__ void cp_commit() {
    asm volatile("cp.async.commit_group;" ::: "memory");
}
__device__ __forceinline__ void cp_wait0() {
    asm volatile("cp.async.wait_group 0;" ::: "memory");
}

// ---------------------------------------------------------------------------
// Kernel 1: QKV GEMM (TF32 mma).  C[8192,2304] = X @ W + bias -> scatter
// (tf32-prerounded bits).  CTA 256 thr, tile 128x128, k-step 32, reg dbuf.
// ---------------------------------------------------------------------------
#define XS_STR 36     // == 4 (mod 32): conflict-free A-frag loads
#define WS_STR 136    // == 8 (mod 32): conflict-free B-frag loads

__global__ __launch_bounds__(256, 2) void qkv_gemm_kernel(
    const float* __restrict__ X, const float* __restrict__ W,
    const float* __restrict__ bias, int B)
{
    __shared__ unsigned Xs[128 * XS_STR];
    __shared__ unsigned Ws[32 * WS_STR];

    const int tid  = threadIdx.x;
    const int lane = tid & 31;
    const int gid  = lane >> 2;
    const int tig  = lane & 3;
    const int w    = tid >> 5;
    const int wm   = w >> 1;               // 0..3
    const int wn   = w & 1;                // 0..1
    const int row0 = blockIdx.y * 128;
    const int col0 = blockIdx.x * 128;

    float c[2][8][4];
#pragma unroll
    for (int mt = 0; mt < 2; mt++)
#pragma unroll
        for (int nt = 0; nt < 8; nt++)
#pragma unroll
            for (int j = 0; j < 4; j++) c[mt][nt][j] = 0.f;

    const int xr = tid >> 1, xk = (tid & 1) * 16;   // X fill: row, k-slice
    const int wr = tid >> 3, wc = (tid & 7) * 16;   // W fill: k-row, col-slice

    float4 xs4[4], ws4[4];
    {
        const float* xsrc = X + (size_t)(row0 + xr) * DIM + xk;
        const float* wsrc = W + (size_t)wr * TD + col0 + wc;
#pragma unroll
        for (int i = 0; i < 4; i++) { xs4[i] = *(const float4*)(xsrc + 4 * i);
                                      ws4[i] = *(const float4*)(wsrc + 4 * i); }
    }

    for (int k0 = 0; k0 < DIM; k0 += 32) {
#pragma unroll
        for (int i = 0; i < 4; i++) {
            *(uint4*)&Xs[xr * XS_STR + xk + 4 * i] =
                make_uint4(tf32u(xs4[i].x), tf32u(xs4[i].y), tf32u(xs4[i].z), tf32u(xs4[i].w));
            *(uint4*)&Ws[wr * WS_STR + wc + 4 * i] =
                make_uint4(tf32u(ws4[i].x), tf32u(ws4[i].y), tf32u(ws4[i].z), tf32u(ws4[i].w));
        }
        __syncthreads();

        if (k0 + 32 < DIM) {
            const float* xsrc = X + (size_t)(row0 + xr) * DIM + k0 + 32 + xk;
            const float* wsrc = W + (size_t)(k0 + 32 + wr) * TD + col0 + wc;
#pragma unroll
            for (int i = 0; i < 4; i++) { xs4[i] = *(const float4*)(xsrc + 4 * i);
                                          ws4[i] = *(const float4*)(wsrc + 4 * i); }
        }

#pragma unroll
        for (int kc = 0; kc < 4; kc++) {
            unsigned a[2][4];
#pragma unroll
            for (int mt = 0; mt < 2; mt++) {
                const unsigned* qp = &Xs[(wm * 32 + mt * 16 + gid) * XS_STR + kc * 8 + tig];
                a[mt][0] = qp[0];
                a[mt][2] = qp[4];
                a[mt][1] = qp[8 * XS_STR];
                a[mt][3] = qp[8 * XS_STR + 4];
            }
#pragma unroll
            for (int nt = 0; nt < 8; nt++) {
                unsigned b0 = Ws[(kc * 8 + tig)     * WS_STR + wn * 64 + nt * 8 + gid];
                unsigned b1 = Ws[(kc * 8 + tig + 4) * WS_STR + wn * 64 + nt * 8 + gid];
                mma8(c[0][nt], a[0], b0, b1);
                mma8(c[1][nt], a[1], b0, b1);
            }
        }
        __syncthreads();
    }

    // epilogue: bias + tf32 preround + scatter into g_qkv[s][b*NH+h][n][d]
    const size_t per_s = (size_t)B * NH * NSEQ * HD;
#pragma unroll
    for (int mt = 0; mt < 2; mt++) {
        const int r_lo = row0 + wm * 32 + mt * 16 + gid;
        const int r_hi = r_lo + 8;
#pragma unroll
        for (int nt = 0; nt < 8; nt++) {
            const int cA = col0 + wn * 64 + nt * 8 + 2 * tig;
#pragma unroll
            for (int e = 0; e < 2; e++) {
                const int cc = cA + e;
                const float bb = __ldg(&bias[cc]);
                const int s  = cc / DIM;
                const int rem = cc - s * DIM;
                const int h  = rem / HD;
                const int d  = rem - h * HD;
#pragma unroll
                for (int half = 0; half < 2; half++) {
                    const int r = half ? r_hi : r_lo;
                    const int b = r >> 12;
                    const int n = r & 4095;
                    const float v = c[mt][nt][half * 2 + e] + bb;
                    g_qkv[(size_t)s * per_s +
                          (((size_t)(b * NH + h)) * NSEQ + n) * HD + d] =
                        __uint_as_float(tf32u(v));
                }
            }
        }
    }
}

// ---------------------------------------------------------------------------
// Kernel 2: flash attention, TF32 mma + cp.async double-buffered K/V.
// grid = (NSEQ/256, B*NH), CTA 512 thr (16 warps), q-tile 256, kv-tile 64.
// k-permutation trick: hw k-slots (tig, tig+4) carry logical k (2tig, 2tig+1)
//  -> phase-1 A/B fragment pairs are contiguous (LDS.64 from natural layout)
//  -> phase-2 P A-fragment == phase-1 S C-fragment (zero shuffles).
// Strides: Q/K 104 (==8 mod 32), V 100 (==4 mod 32) — all conflict-free.
// g_qkv already holds tf32 bits (RNA) — loads are passthrough.
// ---------------------------------------------------------------------------
#define QT 256
#define KVT 64
#define QS_STR 104
#define KS_STR 104
#define VS_STR 100
#define KWORDS (KVT * KS_STR)         // 6656
#define VWORDS (KVT * VS_STR)         // 6400
#define OFF_K  (QT * QS_STR)          // 26624
#define OFF_V  (OFF_K + 2 * KWORDS)   // 39936
#define ATTN_SMEM_WORDS (OFF_V + 2 * VWORDS)
#define ATTN_SMEM_BYTES (ATTN_SMEM_WORDS * 4)   // 210944

__global__ __launch_bounds__(512, 1) void attn_kernel(
    float* __restrict__ out, int B)
{
    extern __shared__ unsigned asmem[];
    unsigned* Qs = asmem;
    const unsigned smemA = (unsigned)__cvta_generic_to_shared(asmem);

    const int tid  = threadIdx.x;
    const int lane = tid & 31;
    const int gid  = lane >> 2;
    const int tig  = lane & 3;
    const int w    = tid >> 5;                  // 0..15: rows [16w, 16w+16)
    const int bh   = blockIdx.y;
    const int q0   = blockIdx.x * QT;

    const size_t per_s = (size_t)B * NH * NSEQ * HD;
    const float* Qg = g_qkv + (size_t)bh * NSEQ * HD;
    const float* Kg = Qg + per_s;
    const float* Vg = Kg + per_s;

    // ---- cp.async fill mapping: 3072 16B-chunks (K: [0,1536), V: rest) ----
    int      fArr[6];
    unsigned fSoff[6];     // word offset inside the K or V buffer
    unsigned fGoff[6];     // float offset inside the 64x96 global tile
#pragma unroll
    for (int i = 0; i < 6; i++) {
        int c   = tid + i * 512;
        int arr = (c >= 1536);
        int rem = c - (arr ? 1536 : 0);
        int r   = rem / 24;
        int ch  = rem - r * 24;
        fArr[i]  = arr;
        fSoff[i] = arr ? (unsigned)(r * VS_STR + ch * 4) : (unsigned)(r * KS_STR + ch * 4);
        fGoff[i] = (unsigned)(r * HD + ch * 4);
    }

    // ---- issue fills for tile 0 (buf 0) ----
    {
        const unsigned kB = smemA + OFF_K * 4;
        const unsigned vB = smemA + OFF_V * 4;
#pragma unroll
        for (int i = 0; i < 6; i++) {
            const float* src = (fArr[i] ? Vg : Kg) + fGoff[i];
            cp16((fArr[i] ? vB : kB) + fSoff[i] * 4, src);
        }
        cp_commit();
    }

    // ---- load Q tile (already tf32 bits — plain copy) ----
    {
        const int row = tid >> 1, dp = (tid & 1) * 48;
        const float* src = Qg + (size_t)(q0 + row) * HD + dp;
#pragma unroll
        for (int i = 0; i < 12; i++)
            *(uint4*)&Qs[row * QS_STR + dp + 4 * i] = *(const uint4*)(src + 4 * i);
    }

    // softmax state + O accumulators
    float m_lo = -INFINITY, m_hi = -INFINITY, l_lo = 0.f, l_hi = 0.f;
    float o[12][4];
#pragma unroll
    for (int nt = 0; nt < 12; nt++)
#pragma unroll
        for (int j = 0; j < 4; j++) o[nt][j] = 0.f;

    const unsigned* qbase = &Qs[(w * 16 + gid) * QS_STR + 2 * tig];

    for (int t = 0; t < NSEQ / KVT; ++t) {
        const int buf = t & 1;
        cp_wait0();
        __syncthreads();              // tile t resident; prev bufs free

        if (t + 1 < NSEQ / KVT) {
            const int nbuf = buf ^ 1;
            const size_t gbase = (size_t)(t + 1) * KVT * HD;
            const unsigned kB = smemA + (OFF_K + nbuf * KWORDS) * 4;
            const unsigned vB = smemA + (OFF_V + nbuf * VWORDS) * 4;
#pragma unroll
            for (int i = 0; i < 6; i++) {
                const float* src = (fArr[i] ? Vg : Kg) + gbase + fGoff[i];
                cp16((fArr[i] ? vB : kB) + fSoff[i] * 4, src);
            }
            cp_commit();
        }

        const unsigned* Kc = asmem + OFF_K + buf * KWORDS;
        const unsigned* Vc = asmem + OFF_V + buf * VWORDS;

        // ---- S = Q K^T : 12 k-chunks x 8 n-tiles (paired LDS.64 frags) ----
        float s[8][4];
#pragma unroll
        for (int nt = 0; nt < 8; nt++)
#pragma unroll
            for (int j = 0; j < 4; j++) s[nt][j] = 0.f;

#pragma unroll
        for (int kc = 0; kc < 12; kc++) {
            uint2 qa = *(const uint2*)&qbase[kc * 8];
            uint2 qb = *(const uint2*)&qbase[8 * QS_STR + kc * 8];
            unsigned a[4] = { qa.x, qb.x, qa.y, qb.y };
#pragma unroll
            for (int nt = 0; nt < 8; nt++) {
                uint2 kk = *(const uint2*)&Kc[(nt * 8 + gid) * KS_STR + kc * 8 + 2 * tig];
                mma8(s[nt], a, kk.x, kk.y);
            }
        }

        // ---- online softmax ----
        float rmax_lo = -INFINITY, rmax_hi = -INFINITY;
#pragma unroll
        for (int nt = 0; nt < 8; nt++) {
            rmax_lo = fmaxf(rmax_lo, fmaxf(s[nt][0], s[nt][1]));
            rmax_hi = fmaxf(rmax_hi, fmaxf(s[nt][2], s[nt][3]));
        }
        rmax_lo = fmaxf(rmax_lo, __shfl_xor_sync(0xffffffffu, rmax_lo, 1));
        rmax_lo = fmaxf(rmax_lo, __shfl_xor_sync(0xffffffffu, rmax_lo, 2));
        rmax_hi = fmaxf(rmax_hi, __shfl_xor_sync(0xffffffffu, rmax_hi, 1));
        rmax_hi = fmaxf(rmax_hi, __shfl_xor_sync(0xffffffffu, rmax_hi, 2));

        const float mn_lo = fmaxf(m_lo, rmax_lo * SCALE);
        const float mn_hi = fmaxf(m_hi, rmax_hi * SCALE);
        const float corr_lo = __expf(m_lo - mn_lo);
        const float corr_hi = __expf(m_hi - mn_hi);
        m_lo = mn_lo; m_hi = mn_hi;

        float sum_lo = 0.f, sum_hi = 0.f;
#pragma unroll
        for (int nt = 0; nt < 8; nt++) {
            float e0 = __expf(fmaf(s[nt][0], SCALE, -mn_lo));
            float e1 = __expf(fmaf(s[nt][1], SCALE, -mn_lo));
            float e2 = __expf(fmaf(s[nt][2], SCALE, -mn_hi));
            float e3 = __expf(fmaf(s[nt][3], SCALE, -mn_hi));
            sum_lo += e0 + e1;
            sum_hi += e2 + e3;
            s[nt][0] = __uint_as_float(tf32u(e0));
            s[nt][1] = __uint_as_float(tf32u(e1));
            s[nt][2] = __uint_as_float(tf32u(e2));
            s[nt][3] = __uint_as_float(tf32u(e3));
        }
        sum_lo += __shfl_xor_sync(0xffffffffu, sum_lo, 1);
        sum_lo += __shfl_xor_sync(0xffffffffu, sum_lo, 2);
        sum_hi += __shfl_xor_sync(0xffffffffu, sum_hi, 1);
        sum_hi += __shfl_xor_sync(0xffffffffu, sum_hi, 2);
        l_lo = l_lo * corr_lo + sum_lo;
        l_hi = l_hi * corr_hi + sum_hi;

#pragma unroll
        for (int nt = 0; nt < 12; nt++) {
            o[nt][0] *= corr_lo; o[nt][1] *= corr_lo;
            o[nt][2] *= corr_hi; o[nt][3] *= corr_hi;
        }

        // ---- O += P @ V : 8 k-chunks x 12 d-tiles  (P C-frag == A-frag) ----
#pragma unroll
        for (int kc = 0; kc < 8; kc++) {
            unsigned a[4] = { __float_as_uint(s[kc][0]), __float_as_uint(s[kc][2]),
                              __float_as_uint(s[kc][1]), __float_as_uint(s[kc][3]) };
            const unsigned* vp = &Vc[(kc * 8 + 2 * tig) * VS_STR + gid];
#pragma unroll
            for (int nt = 0; nt < 12; nt++) {
                unsigned b0 = vp[nt * 8];
                unsigned b1 = vp[VS_STR + nt * 8];
                mma8(o[nt], a, b0, b1);
            }
        }
    }

    // ---- epilogue ----
    const int b = bh >> 3;
    const int h = bh & 7;
    const int r_lo = q0 + w * 16 + gid;
    const int r_hi = r_lo + 8;
    const float inv_lo = 1.f / l_lo;
    const float inv_hi = 1.f / l_hi;
    float* out_lo = out + ((size_t)b * NSEQ + r_lo) * DIM + h * HD;
    float* out_hi = out + ((size_t)b * NSEQ + r_hi) * DIM + h * HD;
#pragma unroll
    for (int nt = 0; nt < 12; nt++) {
        const int d = nt * 8 + 2 * tig;
        *(float2*)&out_lo[d] = make_float2(o[nt][0] * inv_lo, o[nt][1] * inv_lo);
        *(float2*)&out_hi[d] = make_float2(o[nt][2] * inv_hi, o[nt][3] * inv_hi);
    }
}

// ---------------------------------------------------------------------------
extern "C" void kernel_launch(void* const* d_in, const int* in_sizes, int n_in,
                              void* d_out, int out_size)
{
    const float* x    = (const float*)d_in[0];   // (B, N, 768)
    const float* Wqkv = (const float*)d_in[1];   // (768, 2304)
    const float* bqkv = (const float*)d_in[2];   // (2304,)
    float* out = (float*)d_out;

    const int B = in_sizes[0] / (NSEQ * DIM);

    // QKV projection + scatter
    {
        dim3 grid(TD / 128, (B * NSEQ) / 128);
        qkv_gemm_kernel<<<grid, 256>>>(x, Wqkv, bqkv, B);
    }

    // flash attention
    {
        cudaFuncSetAttribute(attn_kernel,
                             cudaFuncAttributeMaxDynamicSharedMemorySize,
                             ATTN_SMEM_BYTES);
        dim3 grid(NSEQ / QT, B * NH);
        attn_kernel<<<grid, 512, ATTN_SMEM_BYTES>>>(out, B);
    }
}

// round 16
// speedup vs baseline: 1.3472x; 1.1404x over previous
#include <cuda_runtime.h>
#include <cuda_bf16.h>
#include <math.h>

// Problem constants (fixed by the dataset)
#define NSEQ 4096
#define DIM  768
#define NH   8
#define HD   96
#define TD   2304
#define MAXB 2
#define SCALE 0.036084391824351615f   // 768^-0.5

// Scratch: [3][B*NH][NSEQ][HD]  (holds tf32-prerounded bits)
__device__ float g_qkv[3ull * MAXB * NH * NSEQ * HD];
// RNA-tf32 prerounded copies of X and W (so GEMM can cp.async raw bits)
__device__ float g_xr[(size_t)MAXB * NSEQ * DIM];
__device__ float g_wr[(size_t)DIM * TD];

// ---------------- helpers ----------------
__device__ __forceinline__ unsigned tf32u(float x) {
    unsigned y; asm("cvt.rna.tf32.f32 %0, %1;" : "=r"(y) : "f"(x)); return y;
}
// D += A(16x8,row,tf32) * B(8x8,col,tf32), fp32 accum
__device__ __forceinline__ void mma8(float* c, const unsigned* a, unsigned b0, unsigned b1) {
    asm volatile(
        "mma.sync.aligned.m16n8k8.row.col.f32.tf32.tf32.f32 "
        "{%0,%1,%2,%3}, {%4,%5,%6,%7}, {%8,%9}, {%0,%1,%2,%3};"
        : "+f"(c[0]), "+f"(c[1]), "+f"(c[2]), "+f"(c[3])
        : "r"(a[0]), "r"(a[1]), "r"(a[2]), "r"(a[3]), "r"(b0), "r"(b1));
}
__device__ __forceinline__ void cp16(unsigned dst, const void* src) {
    asm volatile("cp.async.cg.shared.global [%0], [%1], 16;" :: "r"(dst), "l"(src));
}
__device__ __forceinline__ void cp_commit() {
    asm volatile("cp.async.commit_group;" ::: "memory");
}
__device__ __forceinline__ void cp_wait0() {
    asm volatile("cp.async.wait_group 0;" ::: "memory");
}

// ---------------------------------------------------------------------------
// Kernel 0: RNA-tf32 preround of X and W into g_xr / g_wr.
// ---------------------------------------------------------------------------
__global__ __launch_bounds__(256) void preround_kernel(
    const float4* __restrict__ X, int nx4,
    const float4* __restrict__ W, int nw4)
{
    const int i = blockIdx.x * blockDim.x + threadIdx.x;
    if (i < nx4) {
        float4 v = X[i];
        ((uint4*)g_xr)[i] = make_uint4(tf32u(v.x), tf32u(v.y), tf32u(v.z), tf32u(v.w));
    } else {
        const int j = i - nx4;
        if (j < nw4) {
            float4 v = W[j];
            ((uint4*)g_wr)[j] = make_uint4(tf32u(v.x), tf32u(v.y), tf32u(v.z), tf32u(v.w));
        }
    }
}

// ---------------------------------------------------------------------------
// Kernel 1: QKV GEMM (TF32 mma), cp.async 2-stage pipelined.
// C[8192,2304] = Xr @ Wr + bias -> scatter (tf32-prerounded bits).
// CTA 256 thr (8 warps), tile 128x128, k-step 32.
// smem per stage: Xs 128x36 words + Ws 32x136 words = 8960 words.
// ---------------------------------------------------------------------------
#define XS_STR 36     // == 4 (mod 32): conflict-free A-frag loads
#define WS_STR 136    // == 8 (mod 32): conflict-free B-frag loads
#define GXW   (128 * XS_STR)          // 4608 words
#define GSTAGE (GXW + 32 * WS_STR)    // 8960 words
#define GEMM_SMEM_BYTES (2 * GSTAGE * 4)   // 71680

__global__ __launch_bounds__(256, 2) void qkv_gemm_kernel(
    const float* __restrict__ bias, int B)
{
    extern __shared__ unsigned gsmem[];
    const unsigned smemA = (unsigned)__cvta_generic_to_shared(gsmem);

    const int tid  = threadIdx.x;
    const int lane = tid & 31;
    const int gid  = lane >> 2;
    const int tig  = lane & 3;
    const int w    = tid >> 5;
    const int wm   = w >> 1;               // 0..3
    const int wn   = w & 1;                // 0..1
    const int row0 = blockIdx.y * 128;
    const int col0 = blockIdx.x * 128;

    float c[2][8][4];
#pragma unroll
    for (int mt = 0; mt < 2; mt++)
#pragma unroll
        for (int nt = 0; nt < 8; nt++)
#pragma unroll
            for (int j = 0; j < 4; j++) c[mt][nt][j] = 0.f;

    // ---- per-thread cp.async fill descriptors (8 x 16B chunks/tile) ----
    // chunks 0..1023: X tile (128 rows x 8 k-chunks); 1024..2047: W tile (32 x 32)
    const float* fsrc[8];
    unsigned     fdst[8];    // word offset within a stage
    int          fstp[8];    // float advance per k-tile
#pragma unroll
    for (int i = 0; i < 8; i++) {
        const int cch = tid + i * 256;
        if (cch < 1024) {
            const int row = cch >> 3, k4 = cch & 7;
            fdst[i] = (unsigned)(row * XS_STR + k4 * 4);
            fsrc[i] = g_xr + (size_t)(row0 + row) * DIM + k4 * 4;
            fstp[i] = 32;
        } else {
            const int cc = cch - 1024;
            const int kr = cc >> 5, nc = cc & 31;
            fdst[i] = (unsigned)(GXW + kr * WS_STR + nc * 4);
            fsrc[i] = g_wr + (size_t)kr * TD + col0 + nc * 4;
            fstp[i] = 32 * TD;
        }
    }

    // prologue: issue tile 0 into stage 0
#pragma unroll
    for (int i = 0; i < 8; i++) {
        cp16(smemA + fdst[i] * 4, fsrc[i]);
        fsrc[i] += fstp[i];
    }
    cp_commit();

    const int NKT = DIM / 32;   // 24
    for (int kt = 0; kt < NKT; ++kt) {
        cp_wait0();
        __syncthreads();

        // issue tile kt+1 into the other stage (overlaps compute)
        if (kt + 1 < NKT) {
            const unsigned soff = (unsigned)(((kt + 1) & 1) * GSTAGE) * 4;
#pragma unroll
            for (int i = 0; i < 8; i++) {
                cp16(smemA + soff + fdst[i] * 4, fsrc[i]);
                fsrc[i] += fstp[i];
            }
            cp_commit();
        }

        const unsigned* Xs = gsmem + (kt & 1) * GSTAGE;
        const unsigned* Ws = Xs + GXW;

#pragma unroll
        for (int kc = 0; kc < 4; kc++) {
            unsigned a[2][4];
#pragma unroll
            for (int mt = 0; mt < 2; mt++) {
                const unsigned* qp = &Xs[(wm * 32 + mt * 16 + gid) * XS_STR + kc * 8 + tig];
                a[mt][0] = qp[0];
                a[mt][2] = qp[4];
                a[mt][1] = qp[8 * XS_STR];
                a[mt][3] = qp[8 * XS_STR + 4];
            }
#pragma unroll
            for (int nt = 0; nt < 8; nt++) {
                unsigned b0 = Ws[(kc * 8 + tig)     * WS_STR + wn * 64 + nt * 8 + gid];
                unsigned b1 = Ws[(kc * 8 + tig + 4) * WS_STR + wn * 64 + nt * 8 + gid];
                mma8(c[0][nt], a[0], b0, b1);
                mma8(c[1][nt], a[1], b0, b1);
            }
        }
    }

    // epilogue: bias + tf32 preround + scatter into g_qkv[s][b*NH+h][n][d]
    const size_t per_s = (size_t)B * NH * NSEQ * HD;
#pragma unroll
    for (int mt = 0; mt < 2; mt++) {
        const int r_lo = row0 + wm * 32 + mt * 16 + gid;
        const int r_hi = r_lo + 8;
#pragma unroll
        for (int nt = 0; nt < 8; nt++) {
            const int cA = col0 + wn * 64 + nt * 8 + 2 * tig;
#pragma unroll
            for (int e = 0; e < 2; e++) {
                const int cc = cA + e;
                const float bb = __ldg(&bias[cc]);
                const int s  = cc / DIM;
                const int rem = cc - s * DIM;
                const int h  = rem / HD;
                const int d  = rem - h * HD;
#pragma unroll
                for (int half = 0; half < 2; half++) {
                    const int r = half ? r_hi : r_lo;
                    const int b = r >> 12;
                    const int n = r & 4095;
                    const float v = c[mt][nt][half * 2 + e] + bb;
                    g_qkv[(size_t)s * per_s +
                          (((size_t)(b * NH + h)) * NSEQ + n) * HD + d] =
                        __uint_as_float(tf32u(v));
                }
            }
        }
    }
}

// ---------------------------------------------------------------------------
// Kernel 2: flash attention, TF32 mma + cp.async double-buffered K/V.
// grid = (NSEQ/256, B*NH), CTA 512 thr (16 warps), q-tile 256, kv-tile 64.
// k-permutation trick: hw k-slots (tig, tig+4) carry logical k (2tig, 2tig+1)
//  -> phase-1 A/B fragment pairs are contiguous (LDS.64 from natural layout)
//  -> phase-2 P A-fragment == phase-1 S C-fragment (zero shuffles).
// Strides: Q/K 104 (==8 mod 32), V 100 (==4 mod 32) — all conflict-free.
// g_qkv already holds tf32 bits (RNA) — loads are passthrough.
// ---------------------------------------------------------------------------
#define QT 256
#define KVT 64
#define QS_STR 104
#define KS_STR 104
#define VS_STR 100
#define KWORDS (KVT * KS_STR)         // 6656
#define VWORDS (KVT * VS_STR)         // 6400
#define OFF_K  (QT * QS_STR)          // 26624
#define OFF_V  (OFF_K + 2 * KWORDS)   // 39936
#define ATTN_SMEM_WORDS (OFF_V + 2 * VWORDS)
#define ATTN_SMEM_BYTES (ATTN_SMEM_WORDS * 4)   // 210944

__global__ __launch_bounds__(512, 1) void attn_kernel(
    float* __restrict__ out, int B)
{
    extern __shared__ unsigned asmem[];
    unsigned* Qs = asmem;
    const unsigned smemA = (unsigned)__cvta_generic_to_shared(asmem);

    const int tid  = threadIdx.x;
    const int lane = tid & 31;
    const int gid  = lane >> 2;
    const int tig  = lane & 3;
    const int w    = tid >> 5;                  // 0..15: rows [16w, 16w+16)
    const int bh   = blockIdx.y;
    const int q0   = blockIdx.x * QT;

    const size_t per_s = (size_t)B * NH * NSEQ * HD;
    const float* Qg = g_qkv + (size_t)bh * NSEQ * HD;
    const float* Kg = Qg + per_s;
    const float* Vg = Kg + per_s;

    // ---- cp.async fill mapping: 3072 16B-chunks (K: [0,1536), V: rest) ----
    int      fArr[6];
    unsigned fSoff[6];     // word offset inside the K or V buffer
    unsigned fGoff[6];     // float offset inside the 64x96 global tile
#pragma unroll
    for (int i = 0; i < 6; i++) {
        int c   = tid + i * 512;
        int arr = (c >= 1536);
        int rem = c - (arr ? 1536 : 0);
        int r   = rem / 24;
        int ch  = rem - r * 24;
        fArr[i]  = arr;
        fSoff[i] = arr ? (unsigned)(r * VS_STR + ch * 4) : (unsigned)(r * KS_STR + ch * 4);
        fGoff[i] = (unsigned)(r * HD + ch * 4);
    }

    // ---- issue fills for tile 0 (buf 0) ----
    {
        const unsigned kB = smemA + OFF_K * 4;
        const unsigned vB = smemA + OFF_V * 4;
#pragma unroll
        for (int i = 0; i < 6; i++) {
            const float* src = (fArr[i] ? Vg : Kg) + fGoff[i];
            cp16((fArr[i] ? vB : kB) + fSoff[i] * 4, src);
        }
        cp_commit();
    }

    // ---- load Q tile (already tf32 bits — plain copy) ----
    {
        const int row = tid >> 1, dp = (tid & 1) * 48;
        const float* src = Qg + (size_t)(q0 + row) * HD + dp;
#pragma unroll
        for (int i = 0; i < 12; i++)
            *(uint4*)&Qs[row * QS_STR + dp + 4 * i] = *(const uint4*)(src + 4 * i);
    }

    // softmax state + O accumulators
    float m_lo = -INFINITY, m_hi = -INFINITY, l_lo = 0.f, l_hi = 0.f;
    float o[12][4];
#pragma unroll
    for (int nt = 0; nt < 12; nt++)
#pragma unroll
        for (int j = 0; j < 4; j++) o[nt][j] = 0.f;

    const unsigned* qbase = &Qs[(w * 16 + gid) * QS_STR + 2 * tig];

    for (int t = 0; t < NSEQ / KVT; ++t) {
        const int buf = t & 1;
        cp_wait0();
        __syncthreads();              // tile t resident; prev bufs free

        if (t + 1 < NSEQ / KVT) {
            const int nbuf = buf ^ 1;
            const size_t gbase = (size_t)(t + 1) * KVT * HD;
            const unsigned kB = smemA + (OFF_K + nbuf * KWORDS) * 4;
            const unsigned vB = smemA + (OFF_V + nbuf * VWORDS) * 4;
#pragma unroll
            for (int i = 0; i < 6; i++) {
                const float* src = (fArr[i] ? Vg : Kg) + gbase + fGoff[i];
                cp16((fArr[i] ? vB : kB) + fSoff[i] * 4, src);
            }
            cp_commit();
        }

        const unsigned* Kc = asmem + OFF_K + buf * KWORDS;
        const unsigned* Vc = asmem + OFF_V + buf * VWORDS;

        // ---- S = Q K^T : 12 k-chunks x 8 n-tiles (paired LDS.64 frags) ----
        float s[8][4];
#pragma unroll
        for (int nt = 0; nt < 8; nt++)
#pragma unroll
            for (int j = 0; j < 4; j++) s[nt][j] = 0.f;

#pragma unroll
        for (int kc = 0; kc < 12; kc++) {
            uint2 qa = *(const uint2*)&qbase[kc * 8];
            uint2 qb = *(const uint2*)&qbase[8 * QS_STR + kc * 8];
            unsigned a[4] = { qa.x, qb.x, qa.y, qb.y };
#pragma unroll
            for (int nt = 0; nt < 8; nt++) {
                uint2 kk = *(const uint2*)&Kc[(nt * 8 + gid) * KS_STR + kc * 8 + 2 * tig];
                mma8(s[nt], a, kk.x, kk.y);
            }
        }

        // ---- online softmax ----
        float rmax_lo = -INFINITY, rmax_hi = -INFINITY;
#pragma unroll
        for (int nt = 0; nt < 8; nt++) {
            rmax_lo = fmaxf(rmax_lo, fmaxf(s[nt][0], s[nt][1]));
            rmax_hi = fmaxf(rmax_hi, fmaxf(s[nt][2], s[nt][3]));
        }
        rmax_lo = fmaxf(rmax_lo, __shfl_xor_sync(0xffffffffu, rmax_lo, 1));
        rmax_lo = fmaxf(rmax_lo, __shfl_xor_sync(0xffffffffu, rmax_lo, 2));
        rmax_hi = fmaxf(rmax_hi, __shfl_xor_sync(0xffffffffu, rmax_hi, 1));
        rmax_hi = fmaxf(rmax_hi, __shfl_xor_sync(0xffffffffu, rmax_hi, 2));

        const float mn_lo = fmaxf(m_lo, rmax_lo * SCALE);
        const float mn_hi = fmaxf(m_hi, rmax_hi * SCALE);
        const float corr_lo = __expf(m_lo - mn_lo);
        const float corr_hi = __expf(m_hi - mn_hi);
        m_lo = mn_lo; m_hi = mn_hi;

        float sum_lo = 0.f, sum_hi = 0.f;
#pragma unroll
        for (int nt = 0; nt < 8; nt++) {
            float e0 = __expf(fmaf(s[nt][0], SCALE, -mn_lo));
            float e1 = __expf(fmaf(s[nt][1], SCALE, -mn_lo));
            float e2 = __expf(fmaf(s[nt][2], SCALE, -mn_hi));
            float e3 = __expf(fmaf(s[nt][3], SCALE, -mn_hi));
            sum_lo += e0 + e1;
            sum_hi += e2 + e3;
            s[nt][0] = __uint_as_float(tf32u(e0));
            s[nt][1] = __uint_as_float(tf32u(e1));
            s[nt][2] = __uint_as_float(tf32u(e2));
            s[nt][3] = __uint_as_float(tf32u(e3));
        }
        sum_lo += __shfl_xor_sync(0xffffffffu, sum_lo, 1);
        sum_lo += __shfl_xor_sync(0xffffffffu, sum_lo, 2);
        sum_hi += __shfl_xor_sync(0xffffffffu, sum_hi, 1);
        sum_hi += __shfl_xor_sync(0xffffffffu, sum_hi, 2);
        l_lo = l_lo * corr_lo + sum_lo;
        l_hi = l_hi * corr_hi + sum_hi;

#pragma unroll
        for (int nt = 0; nt < 12; nt++) {
            o[nt][0] *= corr_lo; o[nt][1] *= corr_lo;
            o[nt][2] *= corr_hi; o[nt][3] *= corr_hi;
        }

        // ---- O += P @ V : 8 k-chunks x 12 d-tiles  (P C-frag == A-frag) ----
#pragma unroll
        for (int kc = 0; kc < 8; kc++) {
            unsigned a[4] = { __float_as_uint(s[kc][0]), __float_as_uint(s[kc][2]),
                              __float_as_uint(s[kc][1]), __float_as_uint(s[kc][3]) };
            const unsigned* vp = &Vc[(kc * 8 + 2 * tig) * VS_STR + gid];
#pragma unroll
            for (int nt = 0; nt < 12; nt++) {
                unsigned b0 = vp[nt * 8];
                unsigned b1 = vp[VS_STR + nt * 8];
                mma8(o[nt], a, b0, b1);
            }
        }
    }

    // ---- epilogue ----
    const int b = bh >> 3;
    const int h = bh & 7;
    const int r_lo = q0 + w * 16 + gid;
    const int r_hi = r_lo + 8;
    const float inv_lo = 1.f / l_lo;
    const float inv_hi = 1.f / l_hi;
    float* out_lo = out + ((size_t)b * NSEQ + r_lo) * DIM + h * HD;
    float* out_hi = out + ((size_t)b * NSEQ + r_hi) * DIM + h * HD;
#pragma unroll
    for (int nt = 0; nt < 12; nt++) {
        const int d = nt * 8 + 2 * tig;
        *(float2*)&out_lo[d] = make_float2(o[nt][0] * inv_lo, o[nt][1] * inv_lo);
        *(float2*)&out_hi[d] = make_float2(o[nt][2] * inv_hi, o[nt][3] * inv_hi);
    }
}

// ---------------------------------------------------------------------------
extern "C" void kernel_launch(void* const* d_in, const int* in_sizes, int n_in,
                              void* d_out, int out_size)
{
    const float* x    = (const float*)d_in[0];   // (B, N, 768)
    const float* Wqkv = (const float*)d_in[1];   // (768, 2304)
    const float* bqkv = (const float*)d_in[2];   // (2304,)
    float* out = (float*)d_out;

    const int B = in_sizes[0] / (NSEQ * DIM);

    // Kernel 0: RNA-tf32 preround of X and W
    {
        const int nx4 = in_sizes[0] / 4;
        const int nw4 = (DIM * TD) / 4;
        const int total = nx4 + nw4;
        preround_kernel<<<(total + 255) / 256, 256>>>(
            (const float4*)x, nx4, (const float4*)Wqkv, nw4);
    }

    // Kernel 1: QKV projection + scatter (cp.async pipelined)
    {
        cudaFuncSetAttribute(qkv_gemm_kernel,
                             cudaFuncAttributeMaxDynamicSharedMemorySize,
                             GEMM_SMEM_BYTES);
        dim3 grid(TD / 128, (B * NSEQ) / 128);
        qkv_gemm_kernel<<<grid, 256, GEMM_SMEM_BYTES>>>(bqkv, B);
    }

    // Kernel 2: flash attention
    {
        cudaFuncSetAttribute(attn_kernel,
                             cudaFuncAttributeMaxDynamicSharedMemorySize,
                             ATTN_SMEM_BYTES);
        dim3 grid(NSEQ / QT, B * NH);
        attn_kernel<<<grid, 512, ATTN_SMEM_BYTES>>>(out, B);
    }
}